// round 2
// baseline (speedup 1.0000x reference)
#include <cuda_runtime.h>
#include <cuda_bf16.h>
#include <cstdint>

#define NB   8            // b's per block
#define TPB  128          // 16 threads per b
#define EPS  1e-6f
typedef unsigned long long ull;

__device__ float g_scratch[64];

__global__ void geo_init() {
    g_scratch[threadIdx.x] = 0.0f;
}

__global__ __launch_bounds__(TPB)
void geo_main(const float* __restrict__ R_pred,
              const float* __restrict__ R_gt,
              const float* __restrict__ rot,
              int B)
{
    __shared__ alignas(16) float sRp[NB * 64 * 9];        // 18432 B, staged via TMA bulk
    __shared__ alignas(8)  float sgsym[NB * 12 * 9 * 2];  // 6912 B, duplicated for f32x2
    __shared__ alignas(16) float sgt[NB * 9];             // R_gt slice
    __shared__ float srot[108];
    __shared__ alignas(8) ull mbar;
    __shared__ float ssum;

    const int tid = threadIdx.x;
    const int b0  = blockIdx.x * NB;
    const int nb  = min(NB, B - b0);

    const uint32_t mbar_a = (uint32_t)__cvta_generic_to_shared(&mbar);
    const uint32_t sRp_a  = (uint32_t)__cvta_generic_to_shared(sRp);

    // small tables via plain loads (cheap, overlapped)
    if (tid < 108) srot[tid] = rot[tid];
    if (tid < nb * 9) sgt[tid] = R_gt[(size_t)b0 * 9 + tid];
    if (tid == 0) {
        ssum = 0.0f;
        asm volatile("mbarrier.init.shared.b64 [%0], 1;" :: "r"(mbar_a));
    }
    __syncthreads();

    // one bulk copy for this block's contiguous R_pred slice (nb*2304 bytes, 16B mult)
    const uint32_t bytesRp = (uint32_t)nb * 64u * 9u * 4u;
    if (tid == 0) {
        asm volatile("mbarrier.arrive.expect_tx.shared.b64 _, [%0], %1;"
                     :: "r"(mbar_a), "r"(bytesRp));
        asm volatile("cp.async.bulk.shared::cta.global.mbarrier::complete_tx::bytes "
                     "[%0], [%1], %2, [%3];"
                     :: "r"(sRp_a), "l"(R_pred + (size_t)b0 * 576), "r"(bytesRp), "r"(mbar_a)
                     : "memory");
    }
    // wait (parity phase 0)
    {
        uint32_t done;
        do {
            asm volatile(
                "{\n\t.reg .pred P;\n\t"
                "mbarrier.try_wait.parity.acquire.cta.shared::cta.b64 P, [%1], %2, 0x989680;\n\t"
                "selp.b32 %0, 1, 0, P;\n\t}"
                : "=r"(done) : "r"(mbar_a), "r"(0u) : "memory");
        } while (!done);
    }

    // Gsym[b,s,i,k] = sum_j rot[s,i,j] * R_gt[b,j,k], stored DUPLICATED (x,x) for f32x2
    for (int i = tid; i < nb * 108; i += TPB) {
        int bl = i / 108;
        int r  = i - bl * 108;
        int s  = r / 9;
        int e  = r - s * 9;
        int ii = e / 3, kk = e - 3 * (e / 3);
        const float* ro = srot + s * 9;
        const float* gt = sgt + bl * 9;
        float v = fmaf(ro[ii*3+2], gt[6+kk],
                  fmaf(ro[ii*3+1], gt[3+kk],
                       ro[ii*3+0] * gt[0+kk]));
        float2 d; d.x = v; d.y = v;
        *reinterpret_cast<float2*>(&sgsym[i * 2]) = d;
    }
    __syncthreads();

    const int bl = tid >> 4;           // 0..7
    const int m  = tid & 15;           // candidate group (4 candidates each)
    float cmax = -1e30f;

    if (bl < nb) {
        // 36 floats = 144B, 16B-aligned, conflict-free LDS.128 pattern
        float rp[36];
        const float4* p4 = reinterpret_cast<const float4*>(&sRp[(bl * 64 + m * 4) * 9]);
        #pragma unroll
        for (int k = 0; k < 9; k++) {
            float4 v = p4[k];
            rp[4*k+0] = v.x; rp[4*k+1] = v.y; rp[4*k+2] = v.z; rp[4*k+3] = v.w;
        }

        // pack candidate pairs: a[e]=(c0,c1), bq[e]=(c2,c3)
        ull a[9], bq[9];
        #pragma unroll
        for (int e = 0; e < 9; e++) {
            asm("mov.b64 %0, {%1, %2};" : "=l"(a[e])  : "f"(rp[e]),      "f"(rp[9  + e]));
            asm("mov.b64 %0, {%1, %2};" : "=l"(bq[e]) : "f"(rp[18 + e]), "f"(rp[27 + e]));
        }

        const ull* gsp = reinterpret_cast<const ull*>(&sgsym[(bl * 12) * 18]);
        #pragma unroll
        for (int s = 0; s < 12; s++) {
            ull acc0 = 0ull, acc1 = 0ull;
            #pragma unroll
            for (int e = 0; e < 9; e++) {
                ull gs = gsp[s * 9 + e];   // warp-broadcast ld.shared.b64
                asm("fma.rn.f32x2 %0, %1, %2, %3;" : "=l"(acc0) : "l"(a[e]),  "l"(gs), "l"(acc0));
                asm("fma.rn.f32x2 %0, %1, %2, %3;" : "=l"(acc1) : "l"(bq[e]), "l"(gs), "l"(acc1));
            }
            float t0, t1, t2, t3;
            asm("mov.b64 {%0, %1}, %2;" : "=f"(t0), "=f"(t1) : "l"(acc0));
            asm("mov.b64 {%0, %1}, %2;" : "=f"(t2), "=f"(t3) : "l"(acc1));
            cmax = fmaxf(cmax, fmaxf(fmaxf(t0, t1), fmaxf(t2, t3)));
        }
    }

    // max over the 16 lanes sharing this b
    #pragma unroll
    for (int w = 8; w >= 1; w >>= 1)
        cmax = fmaxf(cmax, __shfl_xor_sync(0xFFFFFFFFu, cmax, w));

    if (m == 0 && bl < nb) {
        float cosv = (cmax - 1.0f) * 0.5f;
        cosv = fminf(fmaxf(cosv, -1.0f + EPS), 1.0f - EPS);
        atomicAdd(&ssum, acosf(cosv));
    }
    __syncthreads();
    if (tid == 0) atomicAdd(&g_scratch[blockIdx.x & 63], ssum);
}

__global__ void geo_final(float* out, float invB) {
    int t = threadIdx.x;                 // 32 threads
    float v = g_scratch[t] + g_scratch[t + 32];
    #pragma unroll
    for (int w = 16; w >= 1; w >>= 1)
        v += __shfl_xor_sync(0xFFFFFFFFu, v, w);
    if (t == 0) out[0] = v * invB;
}

extern "C" void kernel_launch(void* const* d_in, const int* in_sizes, int n_in,
                              void* d_out, int out_size)
{
    const float* R_pred = (const float*)d_in[0];
    const float* R_gt   = (const float*)d_in[1];
    const float* rot    = (const float*)d_in[2];
    float* out = (float*)d_out;

    const int B = in_sizes[1] / 9;

    geo_init<<<1, 64>>>();
    const int grid = (B + NB - 1) / NB;
    geo_main<<<grid, TPB>>>(R_pred, R_gt, rot, B);
    geo_final<<<1, 32>>>(out, 1.0f / (float)B);
}